// round 9
// baseline (speedup 1.0000x reference)
#include <cuda_runtime.h>
#include <math.h>
#include <stdint.h>

#define NN   50000
#define EE   800000
#define FF   768
#define HH   256
#define AA   128
#define AHD  4
#define NCLS 7

// ---------------- scratch (no allocations allowed) ----------------
__device__ __align__(16) float g_h[(size_t)NN * HH];
__device__ __align__(16) float g_agg[(size_t)NN * HH];
__device__ __align__(16) float g_t[(size_t)NN * HH];
__device__ int   g_deg[NN];
__device__ int   g_rowstart[NN + 1];
__device__ int   g_cursor[NN];
__device__ int   g_srclist[EE];
__device__ float g_logits[AHD * NN];
__device__ float g_smax[AHD];
__device__ float g_srsum[AHD];
__device__ float g_z[AHD * HH];

// ---------------- small utility kernels ----------------
__global__ void zero_kernel() {
    int i = blockIdx.x * blockDim.x + threadIdx.x;
    if (i < NN) g_deg[i] = 0;
    if (i < AHD * HH) g_z[i] = 0.f;
}

__global__ void hist_kernel(const int* __restrict__ ei) {
    int e = blockIdx.x * blockDim.x + threadIdx.x;
    if (e < EE) atomicAdd(&g_deg[ei[EE + e]], 1);
}

__global__ __launch_bounds__(1024) void scan_kernel() {
    __shared__ int ssum[1024];
    int tid = threadIdx.x;
    const int CH = (NN + 1023) / 1024;
    int base = tid * CH;
    int s = 0;
    for (int i = 0; i < CH; i++) {
        int idx = base + i;
        if (idx < NN) s += g_deg[idx];
    }
    ssum[tid] = s;
    __syncthreads();
    for (int off = 1; off < 1024; off <<= 1) {
        int v = 0;
        if (tid >= off) v = ssum[tid - off];
        __syncthreads();
        ssum[tid] += v;
        __syncthreads();
    }
    int run = (tid == 0) ? 0 : ssum[tid - 1];
    for (int i = 0; i < CH; i++) {
        int idx = base + i;
        if (idx < NN) {
            g_rowstart[idx] = run;
            g_cursor[idx]   = run;
            run += g_deg[idx];
        }
    }
    if (tid == 1023) g_rowstart[NN] = run;
}

__global__ void fill_kernel(const int* __restrict__ ei) {
    int e = blockIdx.x * blockDim.x + threadIdx.x;
    if (e < EE) {
        int d = ei[EE + e];
        int pos = atomicAdd(&g_cursor[d], 1);
        g_srclist[pos] = ei[e];
    }
}

// ---------------- GIN aggregation: one warp per destination node ----------------
__device__ __forceinline__ float4 f4add(float4 a, float4 b) {
    return make_float4(a.x + b.x, a.y + b.y, a.z + b.z, a.w + b.w);
}

__global__ __launch_bounds__(256) void gin_agg_kernel(const float* __restrict__ epsv, int layer) {
    int gtid = blockIdx.x * blockDim.x + threadIdx.x;
    int node = gtid >> 5;
    int lane = gtid & 31;
    if (node >= NN) return;
    int s = g_rowstart[node];
    int e = g_rowstart[node + 1];
    float4 acc0 = make_float4(0, 0, 0, 0);
    float4 acc1 = make_float4(0, 0, 0, 0);
    for (int i = s; i < e; i++) {
        int src = g_srclist[i];
        const float4* r = (const float4*)(g_h + (size_t)src * HH);
        acc0 = f4add(acc0, r[lane]);
        acc1 = f4add(acc1, r[lane + 32]);
    }
    float ep = 1.f + epsv[layer];
    const float4* hr = (const float4*)(g_h + (size_t)node * HH);
    float4 h0 = hr[lane], h1 = hr[lane + 32];
    float4* ar = (float4*)(g_agg + (size_t)node * HH);
    ar[lane]      = make_float4(ep * h0.x + acc0.x, ep * h0.y + acc0.y, ep * h0.z + acc0.z, ep * h0.w + acc0.w);
    ar[lane + 32] = make_float4(ep * h1.x + acc1.x, ep * h1.y + acc1.y, ep * h1.z + acc1.z, ep * h1.w + acc1.w);
}

// ---------------- 128x128x16 register-tiled fp32 GEMM, bias fused ----------------
__global__ __launch_bounds__(256, 2) void gemm_bias_kernel(
    const float* __restrict__ A, const float* __restrict__ B,
    const float* __restrict__ bias, float* __restrict__ C,
    int M, int N, int K)
{
    __shared__ float As[16][128];
    __shared__ float Bs[16][128];
    int tid = threadIdx.x;
    int tx = tid & 15, ty = tid >> 4;
    int rowBase = blockIdx.y * 128;
    int colBase = blockIdx.x * 128;

    float acc[8][8];
#pragma unroll
    for (int i = 0; i < 8; i++)
#pragma unroll
        for (int j = 0; j < 8; j++) acc[i][j] = 0.f;

    for (int k0 = 0; k0 < K; k0 += 16) {
#pragma unroll
        for (int i = 0; i < 2; i++) {
            int f4i = tid * 2 + i;
            int ar = f4i >> 2, ac = (f4i & 3) * 4;
            int grow = rowBase + ar;
            float4 v = make_float4(0, 0, 0, 0);
            if (grow < M) v = *(const float4*)(A + (size_t)grow * K + k0 + ac);
            As[ac + 0][ar] = v.x; As[ac + 1][ar] = v.y;
            As[ac + 2][ar] = v.z; As[ac + 3][ar] = v.w;
        }
#pragma unroll
        for (int i = 0; i < 2; i++) {
            int f4i = tid * 2 + i;
            int br = f4i >> 5, bc = (f4i & 31) * 4;
            float4 v = *(const float4*)(B + (size_t)(k0 + br) * N + colBase + bc);
            *(float4*)&Bs[br][bc] = v;
        }
        __syncthreads();
#pragma unroll
        for (int k = 0; k < 16; k++) {
            float4 a0 = *(float4*)&As[k][ty * 8];
            float4 a1 = *(float4*)&As[k][ty * 8 + 4];
            float4 b0 = *(float4*)&Bs[k][tx * 8];
            float4 b1 = *(float4*)&Bs[k][tx * 8 + 4];
            float aa[8] = {a0.x, a0.y, a0.z, a0.w, a1.x, a1.y, a1.z, a1.w};
            float bb[8] = {b0.x, b0.y, b0.z, b0.w, b1.x, b1.y, b1.z, b1.w};
#pragma unroll
            for (int i = 0; i < 8; i++)
#pragma unroll
                for (int j = 0; j < 8; j++) acc[i][j] += aa[i] * bb[j];
        }
        __syncthreads();
    }

    float bv[8];
#pragma unroll
    for (int j = 0; j < 8; j++) bv[j] = bias[colBase + tx * 8 + j];
#pragma unroll
    for (int i = 0; i < 8; i++) {
        int grow = rowBase + ty * 8 + i;
        if (grow < M) {
            float4 o0 = make_float4(acc[i][0] + bv[0], acc[i][1] + bv[1], acc[i][2] + bv[2], acc[i][3] + bv[3]);
            float4 o1 = make_float4(acc[i][4] + bv[4], acc[i][5] + bv[5], acc[i][6] + bv[6], acc[i][7] + bv[7]);
            *(float4*)(C + (size_t)grow * N + colBase + tx * 8)     = o0;
            *(float4*)(C + (size_t)grow * N + colBase + tx * 8 + 4) = o1;
        }
    }
}

// ---------------- LayerNorm (+relu, + optional residual), warp per row ----------------
__global__ __launch_bounds__(256) void ln_relu_kernel(
    const float* __restrict__ in, const float* __restrict__ gamma,
    const float* __restrict__ beta, const float* __restrict__ resid,
    float* __restrict__ outp)
{
    int gtid = blockIdx.x * blockDim.x + threadIdx.x;
    int row = gtid >> 5;
    int lane = gtid & 31;
    if (row >= NN) return;
    const float* r = in + (size_t)row * HH;
    float v[8];
    float s = 0.f, sq = 0.f;
#pragma unroll
    for (int j = 0; j < 8; j++) {
        float x = r[lane + 32 * j];
        v[j] = x;
        s += x;
        sq += x * x;
    }
#pragma unroll
    for (int off = 16; off; off >>= 1) {
        s  += __shfl_xor_sync(0xffffffffu, s, off);
        sq += __shfl_xor_sync(0xffffffffu, sq, off);
    }
    float mean = s * (1.f / HH);
    float var  = sq * (1.f / HH) - mean * mean;
    float rstd = rsqrtf(var + 1e-5f);
    float* o = outp + (size_t)row * HH;
    const float* rr = resid ? resid + (size_t)row * HH : nullptr;
#pragma unroll
    for (int j = 0; j < 8; j++) {
        int c = lane + 32 * j;
        float y = (v[j] - mean) * rstd * gamma[c] + beta[c];
        y = fmaxf(y, 0.f);
        if (rr) y += rr[c];
        o[c] = y;
    }
}

// ---------------- attention logits: GEMM tile + tanh*w2 row-reduce epilogue ----------------
__global__ __launch_bounds__(256) void attn_logits_kernel(
    const float* __restrict__ h, const float* __restrict__ W1,
    const float* __restrict__ b1, const float* __restrict__ W2,
    const float* __restrict__ b2, float* __restrict__ logits)
{
    __shared__ float As[16][128];
    __shared__ float Bs[16][128];
    __shared__ float red[128][17];
    int tid = threadIdx.x;
    int tx = tid & 15, ty = tid >> 4;
    int head = blockIdx.x;
    int rowBase = blockIdx.y * 128;
    const float* B = W1 + (size_t)head * HH * AA;

    float acc[8][8];
#pragma unroll
    for (int i = 0; i < 8; i++)
#pragma unroll
        for (int j = 0; j < 8; j++) acc[i][j] = 0.f;

    for (int k0 = 0; k0 < HH; k0 += 16) {
#pragma unroll
        for (int i = 0; i < 2; i++) {
            int f4i = tid * 2 + i;
            int ar = f4i >> 2, ac = (f4i & 3) * 4;
            int grow = rowBase + ar;
            float4 v = make_float4(0, 0, 0, 0);
            if (grow < NN) v = *(const float4*)(h + (size_t)grow * HH + k0 + ac);
            As[ac + 0][ar] = v.x; As[ac + 1][ar] = v.y;
            As[ac + 2][ar] = v.z; As[ac + 3][ar] = v.w;
        }
#pragma unroll
        for (int i = 0; i < 2; i++) {
            int f4i = tid * 2 + i;
            int br = f4i >> 5, bc = (f4i & 31) * 4;
            float4 v = *(const float4*)(B + (size_t)(k0 + br) * AA + bc);
            *(float4*)&Bs[br][bc] = v;
        }
        __syncthreads();
#pragma unroll
        for (int k = 0; k < 16; k++) {
            float4 a0 = *(float4*)&As[k][ty * 8];
            float4 a1 = *(float4*)&As[k][ty * 8 + 4];
            float4 b0 = *(float4*)&Bs[k][tx * 8];
            float4 b1 = *(float4*)&Bs[k][tx * 8 + 4];
            float aa[8] = {a0.x, a0.y, a0.z, a0.w, a1.x, a1.y, a1.z, a1.w};
            float bb[8] = {b0.x, b0.y, b0.z, b0.w, b1.x, b1.y, b1.z, b1.w};
#pragma unroll
            for (int i = 0; i < 8; i++)
#pragma unroll
                for (int j = 0; j < 8; j++) acc[i][j] += aa[i] * bb[j];
        }
        __syncthreads();
    }

    float b1v[8], w2v[8];
#pragma unroll
    for (int j = 0; j < 8; j++) {
        int col = tx * 8 + j;
        b1v[j] = b1[head * AA + col];
        w2v[j] = W2[head * AA + col];
    }
#pragma unroll
    for (int i = 0; i < 8; i++) {
        float p = 0.f;
#pragma unroll
        for (int j = 0; j < 8; j++) {
            float v = tanhf(acc[i][j] + b1v[j]);
            p += v * w2v[j];
        }
        red[ty * 8 + i][tx] = p;
    }
    __syncthreads();
    if (tid < 128) {
        float sum = 0.f;
#pragma unroll
        for (int t = 0; t < 16; t++) sum += red[tid][t];
        int grow = rowBase + tid;
        if (grow < NN) logits[head * NN + grow] = sum + b2[head];
    }
}

// ---------------- softmax stats: one block per head ----------------
__global__ __launch_bounds__(1024) void softmax_stats_kernel() {
    int k = blockIdx.x;
    const float* l = g_logits + k * NN;
    __shared__ float red[1024];
    int tid = threadIdx.x;
    float mx = -1e30f;
    for (int i = tid; i < NN; i += 1024) mx = fmaxf(mx, l[i]);
    red[tid] = mx;
    __syncthreads();
    for (int off = 512; off; off >>= 1) {
        if (tid < off) red[tid] = fmaxf(red[tid], red[tid + off]);
        __syncthreads();
    }
    mx = red[0];
    __syncthreads();
    float s = 0.f;
    for (int i = tid; i < NN; i += 1024) s += expf(l[i] - mx);
    red[tid] = s;
    __syncthreads();
    for (int off = 512; off; off >>= 1) {
        if (tid < off) red[tid] += red[tid + off];
        __syncthreads();
    }
    if (tid == 0) {
        g_smax[k]  = mx;
        g_srsum[k] = 1.f / red[0];
    }
}

// ---------------- pooling: write attn output + accumulate z ----------------
__global__ __launch_bounds__(256) void pool_kernel(const float* __restrict__ h, float* __restrict__ out) {
    __shared__ float a_s[256 * 4];
    int tid = threadIdx.x;
    int n0 = blockIdx.x * 256;
    int n = n0 + tid;
#pragma unroll
    for (int k = 0; k < AHD; k++) {
        float a = 0.f;
        if (n < NN) {
            a = expf(g_logits[k * NN + n] - g_smax[k]) * g_srsum[k];
            out[7 + (size_t)n * AHD + k] = a;
        }
        a_s[tid * 4 + k] = a;
    }
    __syncthreads();
    float zr[4] = {0.f, 0.f, 0.f, 0.f};
    int nmax = min(256, NN - n0);
    for (int i = 0; i < nmax; i++) {
        float hv = h[(size_t)(n0 + i) * HH + tid];
        float4 av = *(float4*)&a_s[i * 4];
        zr[0] += av.x * hv;
        zr[1] += av.y * hv;
        zr[2] += av.z * hv;
        zr[3] += av.w * hv;
    }
#pragma unroll
    for (int k = 0; k < AHD; k++) atomicAdd(&g_z[k * HH + tid], zr[k]);
}

// ---------------- classifier: single block ----------------
__global__ __launch_bounds__(256) void classifier_kernel(
    const float* __restrict__ Wc1, const float* __restrict__ bc1,
    const float* __restrict__ g1,  const float* __restrict__ b1,
    const float* __restrict__ Wc2, const float* __restrict__ bc2,
    const float* __restrict__ g2,  const float* __restrict__ b2,
    const float* __restrict__ Wc3, const float* __restrict__ bc3,
    float* __restrict__ out)
{
    __shared__ float sh[256];
    __shared__ float redA[256];
    __shared__ float redB[256];
    int tid = threadIdx.x;
    float za = 0.25f * (g_z[tid] + g_z[256 + tid] + g_z[512 + tid] + g_z[768 + tid]);
    sh[tid] = za;
    __syncthreads();

    // layer 1: 256 -> 128, LN, relu
    float c = 0.f;
    if (tid < 128) {
        for (int d = 0; d < 256; d++) c += sh[d] * Wc1[d * 128 + tid];
        c += bc1[tid];
    }
    redA[tid] = (tid < 128) ? c : 0.f;
    redB[tid] = (tid < 128) ? c * c : 0.f;
    __syncthreads();
    for (int off = 128; off; off >>= 1) {
        if (tid < off) { redA[tid] += redA[tid + off]; redB[tid] += redB[tid + off]; }
        __syncthreads();
    }
    float mean = redA[0] / 128.f;
    float var  = redB[0] / 128.f - mean * mean;
    float rstd = rsqrtf(var + 1e-5f);
    __syncthreads();
    if (tid < 128) sh[tid] = fmaxf((c - mean) * rstd * g1[tid] + b1[tid], 0.f);
    __syncthreads();

    // layer 2: 128 -> 64, LN, relu
    float c2 = 0.f;
    if (tid < 64) {
        for (int d = 0; d < 128; d++) c2 += sh[d] * Wc2[d * 64 + tid];
        c2 += bc2[tid];
    }
    redA[tid] = (tid < 64) ? c2 : 0.f;
    redB[tid] = (tid < 64) ? c2 * c2 : 0.f;
    __syncthreads();
    for (int off = 128; off; off >>= 1) {
        if (tid < off) { redA[tid] += redA[tid + off]; redB[tid] += redB[tid + off]; }
        __syncthreads();
    }
    mean = redA[0] / 64.f;
    var  = redB[0] / 64.f - mean * mean;
    rstd = rsqrtf(var + 1e-5f);
    __syncthreads();
    if (tid < 64) sh[tid] = fmaxf((c2 - mean) * rstd * g2[tid] + b2[tid], 0.f);
    __syncthreads();

    // layer 3: 64 -> 7, softmax
    if (tid < NCLS) {
        float lg = 0.f;
        for (int d = 0; d < 64; d++) lg += sh[d] * Wc3[d * NCLS + tid];
        redA[tid] = lg + bc3[tid];
    }
    __syncthreads();
    if (tid == 0) {
        float mx = -1e30f;
        for (int i = 0; i < NCLS; i++) mx = fmaxf(mx, redA[i]);
        float s = 0.f;
        for (int i = 0; i < NCLS; i++) s += expf(redA[i] - mx);
        float rs = 1.f / s;
        for (int i = 0; i < NCLS; i++) out[i] = expf(redA[i] - mx) * rs;
    }
}

// ---------------- launcher ----------------
extern "C" void kernel_launch(void* const* d_in, const int* in_sizes, int n_in,
                              void* d_out, int out_size)
{
    const float* x     = (const float*)d_in[0];
    const int*   ei    = (const int*)  d_in[1];
    const float* W_in  = (const float*)d_in[2];
    const float* b_in  = (const float*)d_in[3];
    const float* gW1   = (const float*)d_in[4];
    const float* gb1   = (const float*)d_in[5];
    const float* glng  = (const float*)d_in[6];
    const float* glnb  = (const float*)d_in[7];
    const float* gW2   = (const float*)d_in[8];
    const float* gb2   = (const float*)d_in[9];
    const float* eps   = (const float*)d_in[10];
    const float* lng   = (const float*)d_in[11];
    const float* lnb   = (const float*)d_in[12];
    const float* aW1   = (const float*)d_in[13];
    const float* ab1   = (const float*)d_in[14];
    const float* aW2   = (const float*)d_in[15];
    const float* ab2   = (const float*)d_in[16];
    const float* Wc1   = (const float*)d_in[17];
    const float* bc1   = (const float*)d_in[18];
    const float* lc1g  = (const float*)d_in[19];
    const float* lc1b  = (const float*)d_in[20];
    const float* Wc2   = (const float*)d_in[21];
    const float* bc2   = (const float*)d_in[22];
    const float* lc2g  = (const float*)d_in[23];
    const float* lc2b  = (const float*)d_in[24];
    const float* Wc3   = (const float*)d_in[25];
    const float* bc3   = (const float*)d_in[26];
    float* out = (float*)d_out;

    float *p_h, *p_agg, *p_t;
    cudaGetSymbolAddress((void**)&p_h, g_h);
    cudaGetSymbolAddress((void**)&p_agg, g_agg);
    cudaGetSymbolAddress((void**)&p_t, g_t);
    float* p_logits;
    cudaGetSymbolAddress((void**)&p_logits, g_logits);

    const int MB = (NN + 127) / 128;      // 391 row tiles
    const int WARP_BLKS = (NN * 32 + 255) / 256;   // 6250
    const int ROW_BLKS  = (NN + 7) / 8;            // 6250
    const int EDGE_BLKS = (EE + 255) / 256;        // 3125
    const int POOL_BLKS = (NN + 255) / 256;        // 196

    // CSR build + scratch zero
    zero_kernel<<<POOL_BLKS, 256>>>();
    hist_kernel<<<EDGE_BLKS, 256>>>(ei);
    scan_kernel<<<1, 1024>>>();
    fill_kernel<<<EDGE_BLKS, 256>>>(ei);

    // input projection: h = x @ W_in + b_in
    gemm_bias_kernel<<<dim3(HH / 128, MB), 256>>>(x, W_in, b_in, p_h, NN, HH, FF);

    // GIN layers
    for (int l = 0; l < 2; l++) {
        gin_agg_kernel<<<WARP_BLKS, 256>>>(eps, l);
        gemm_bias_kernel<<<dim3(HH / 128, MB), 256>>>(p_agg, gW1 + (size_t)l * HH * HH,
                                                      gb1 + l * HH, p_t, NN, HH, HH);
        ln_relu_kernel<<<ROW_BLKS, 256>>>(p_t, glng + l * HH, glnb + l * HH, nullptr, p_t);
        gemm_bias_kernel<<<dim3(HH / 128, MB), 256>>>(p_t, gW2 + (size_t)l * HH * HH,
                                                      gb2 + l * HH, p_agg, NN, HH, HH);
        ln_relu_kernel<<<ROW_BLKS, 256>>>(p_agg, lng + l * HH, lnb + l * HH, p_h, p_h);
    }

    // attention pooling
    attn_logits_kernel<<<dim3(AHD, MB), 256>>>(p_h, aW1, ab1, aW2, ab2, p_logits);
    softmax_stats_kernel<<<AHD, 1024>>>();
    pool_kernel<<<POOL_BLKS, 256>>>(p_h, out);

    // classifier head
    classifier_kernel<<<1, 256>>>(Wc1, bc1, lc1g, lc1b, Wc2, bc2, lc2g, lc2b, Wc3, bc3, out);
}

// round 10
// speedup vs baseline: 1.1540x; 1.1540x over previous
#include <cuda_runtime.h>
#include <math.h>
#include <stdint.h>

#define NN   50000
#define EE   800000
#define FF   768
#define HH   256
#define AA   128
#define AHD  4
#define NCLS 7

// ---------------- scratch (no allocations allowed) ----------------
__device__ __align__(16) float g_h[(size_t)NN * HH];
__device__ __align__(16) float g_agg[(size_t)NN * HH];
__device__ __align__(16) float g_t[(size_t)NN * HH];
__device__ int   g_deg[NN];
__device__ int   g_rowstart[NN + 1];
__device__ int   g_cursor[NN];
__device__ int   g_srclist[EE];
__device__ float g_logits[AHD * NN];
__device__ float g_smax[AHD];
__device__ float g_srsum[AHD];
__device__ float g_z[AHD * HH];

// ---------------- small utility kernels ----------------
__global__ void zero_kernel() {
    int i = blockIdx.x * blockDim.x + threadIdx.x;
    if (i < NN) g_deg[i] = 0;
    if (i < AHD * HH) g_z[i] = 0.f;
    if (i < AHD * NN) g_logits[i] = 0.f;
}

__global__ void hist_kernel(const int* __restrict__ ei) {
    int e = blockIdx.x * blockDim.x + threadIdx.x;
    if (e < EE) atomicAdd(&g_deg[ei[EE + e]], 1);
}

__global__ __launch_bounds__(1024) void scan_kernel() {
    __shared__ int ssum[1024];
    int tid = threadIdx.x;
    const int CH = (NN + 1023) / 1024;
    int base = tid * CH;
    int s = 0;
    for (int i = 0; i < CH; i++) {
        int idx = base + i;
        if (idx < NN) s += g_deg[idx];
    }
    ssum[tid] = s;
    __syncthreads();
    for (int off = 1; off < 1024; off <<= 1) {
        int v = 0;
        if (tid >= off) v = ssum[tid - off];
        __syncthreads();
        ssum[tid] += v;
        __syncthreads();
    }
    int run = (tid == 0) ? 0 : ssum[tid - 1];
    for (int i = 0; i < CH; i++) {
        int idx = base + i;
        if (idx < NN) {
            g_rowstart[idx] = run;
            g_cursor[idx]   = run;
            run += g_deg[idx];
        }
    }
    if (tid == 1023) g_rowstart[NN] = run;
}

__global__ void fill_kernel(const int* __restrict__ ei) {
    int e = blockIdx.x * blockDim.x + threadIdx.x;
    if (e < EE) {
        int d = ei[EE + e];
        int pos = atomicAdd(&g_cursor[d], 1);
        g_srclist[pos] = ei[e];
    }
}

// ---------------- GIN aggregation: one warp per destination node ----------------
__device__ __forceinline__ float4 f4add(float4 a, float4 b) {
    return make_float4(a.x + b.x, a.y + b.y, a.z + b.z, a.w + b.w);
}

__global__ __launch_bounds__(256) void gin_agg_kernel(const float* __restrict__ epsv, int layer) {
    int gtid = blockIdx.x * blockDim.x + threadIdx.x;
    int node = gtid >> 5;
    int lane = gtid & 31;
    if (node >= NN) return;
    int s = g_rowstart[node];
    int e = g_rowstart[node + 1];
    float4 acc0 = make_float4(0, 0, 0, 0);
    float4 acc1 = make_float4(0, 0, 0, 0);
    for (int i = s; i < e; i++) {
        int src = g_srclist[i];
        const float4* r = (const float4*)(g_h + (size_t)src * HH);
        acc0 = f4add(acc0, r[lane]);
        acc1 = f4add(acc1, r[lane + 32]);
    }
    float ep = 1.f + epsv[layer];
    const float4* hr = (const float4*)(g_h + (size_t)node * HH);
    float4 h0 = hr[lane], h1 = hr[lane + 32];
    float4* ar = (float4*)(g_agg + (size_t)node * HH);
    ar[lane]      = make_float4(ep * h0.x + acc0.x, ep * h0.y + acc0.y, ep * h0.z + acc0.z, ep * h0.w + acc0.w);
    ar[lane + 32] = make_float4(ep * h1.x + acc1.x, ep * h1.y + acc1.y, ep * h1.z + acc1.z, ep * h1.w + acc1.w);
}

// ---------------- split-TF32 tensor-core GEMM ----------------
// C[M,N] = A[M,K] @ B[K,N] via mma.sync.m16n8k8.tf32 with 3xTF32 split.
// Block tile 128x64, K-chunk 32, 8 warps (warpM 0-3 x warpN 0-1), warp tile 32x32.
// MODE 0: C = A@B + bias
// MODE 1: attention epilogue -> logits[head][row] += sum_col tanh(acc + b1)*w2

__device__ __forceinline__ uint32_t f2tf32(float x) {
    uint32_t u;
    asm("cvt.rna.tf32.f32 %0, %1;" : "=r"(u) : "f"(x));
    return u;
}

__device__ __forceinline__ void mma8(float* d, const uint32_t* a, const uint32_t* b) {
    asm volatile(
        "mma.sync.aligned.m16n8k8.row.col.f32.tf32.tf32.f32 "
        "{%0,%1,%2,%3}, {%4,%5,%6,%7}, {%8,%9}, {%0,%1,%2,%3};"
        : "+f"(d[0]), "+f"(d[1]), "+f"(d[2]), "+f"(d[3])
        : "r"(a[0]), "r"(a[1]), "r"(a[2]), "r"(a[3]), "r"(b[0]), "r"(b[1]));
}

#define TFS_SMEM_WORDS (128 * 36 * 2 + 64 * 36 * 2)

template <int MODE>
__global__ __launch_bounds__(256, 2) void gemm_tf32_kernel(
    const float* __restrict__ A, const float* __restrict__ Bm,
    const float* __restrict__ bias, float* __restrict__ C,
    int M, int N, int K,
    const float* __restrict__ ab1, const float* __restrict__ aw2,
    float* __restrict__ logits)
{
    extern __shared__ uint32_t sm[];
    uint32_t* Ah = sm;
    uint32_t* Al = Ah + 128 * 36;
    uint32_t* Bh = Al + 128 * 36;
    uint32_t* Bl = Bh + 64 * 36;

    int tid = threadIdx.x;
    int wid = tid >> 5;
    int lane = tid & 31;
    int warpM = wid >> 1;          // 0..3 (32 rows each)
    int warpN = wid & 1;           // 0..1 (32 cols each)
    int rowBase = blockIdx.y * 128;
    int colBase = blockIdx.x * 64;
    int head = (MODE == 1) ? blockIdx.z : 0;
    const float* B = (MODE == 1) ? Bm + (size_t)head * HH * AA : Bm;

    float acc[2][4][4];
#pragma unroll
    for (int mt = 0; mt < 2; mt++)
#pragma unroll
        for (int nt = 0; nt < 4; nt++)
#pragma unroll
            for (int r = 0; r < 4; r++) acc[mt][nt][r] = 0.f;

    for (int k0 = 0; k0 < K; k0 += 32) {
        // ---- stage A (128x32) hi/lo ----
#pragma unroll
        for (int i = 0; i < 4; i++) {
            int f4id = tid + 256 * i;          // 0..1023
            int row = f4id >> 3;               // 8 float4 per row
            int kc = (f4id & 7) << 2;
            int grow = rowBase + row;
            float4 v = make_float4(0, 0, 0, 0);
            if (grow < M) v = *(const float4*)(A + (size_t)grow * K + k0 + kc);
            uint4 hi, lo;
            hi.x = f2tf32(v.x); lo.x = f2tf32(v.x - __uint_as_float(hi.x));
            hi.y = f2tf32(v.y); lo.y = f2tf32(v.y - __uint_as_float(hi.y));
            hi.z = f2tf32(v.z); lo.z = f2tf32(v.z - __uint_as_float(hi.z));
            hi.w = f2tf32(v.w); lo.w = f2tf32(v.w - __uint_as_float(hi.w));
            *(uint4*)&Ah[row * 36 + kc] = hi;
            *(uint4*)&Al[row * 36 + kc] = lo;
        }
        // ---- stage B (32x64) transposed hi/lo: Bs[n][k] ----
#pragma unroll
        for (int i = 0; i < 2; i++) {
            int f4id = tid + 256 * i;          // 0..511
            int kk = f4id >> 4;                // 16 float4 per k-row
            int nc = (f4id & 15) << 2;
            float4 v = *(const float4*)(B + (size_t)(k0 + kk) * N + colBase + nc);
            float vv[4] = {v.x, v.y, v.z, v.w};
#pragma unroll
            for (int c = 0; c < 4; c++) {
                uint32_t hi = f2tf32(vv[c]);
                uint32_t lo = f2tf32(vv[c] - __uint_as_float(hi));
                Bh[(nc + c) * 36 + kk] = hi;
                Bl[(nc + c) * 36 + kk] = lo;
            }
        }
        __syncthreads();

#pragma unroll
        for (int ksub = 0; ksub < 4; ksub++) {
            int kof = ksub * 8;
            uint32_t Af_h[2][4], Af_l[2][4];
#pragma unroll
            for (int mt = 0; mt < 2; mt++) {
                int mrow = warpM * 32 + mt * 16 + (lane >> 2);
                int base = mrow * 36 + kof + (lane & 3);
                Af_h[mt][0] = Ah[base];
                Af_h[mt][1] = Ah[base + 8 * 36];
                Af_h[mt][2] = Ah[base + 4];
                Af_h[mt][3] = Ah[base + 8 * 36 + 4];
                Af_l[mt][0] = Al[base];
                Af_l[mt][1] = Al[base + 8 * 36];
                Af_l[mt][2] = Al[base + 4];
                Af_l[mt][3] = Al[base + 8 * 36 + 4];
            }
            uint32_t Bf_h[4][2], Bf_l[4][2];
#pragma unroll
            for (int nt = 0; nt < 4; nt++) {
                int n = warpN * 32 + nt * 8 + (lane >> 2);
                int bb = n * 36 + kof + (lane & 3);
                Bf_h[nt][0] = Bh[bb];
                Bf_h[nt][1] = Bh[bb + 4];
                Bf_l[nt][0] = Bl[bb];
                Bf_l[nt][1] = Bl[bb + 4];
            }
#pragma unroll
            for (int mt = 0; mt < 2; mt++)
#pragma unroll
                for (int nt = 0; nt < 4; nt++) {
                    mma8(acc[mt][nt], Af_h[mt], Bf_h[nt]);
                    mma8(acc[mt][nt], Af_l[mt], Bf_h[nt]);
                    mma8(acc[mt][nt], Af_h[mt], Bf_l[nt]);
                }
        }
        __syncthreads();
    }

    if (MODE == 0) {
#pragma unroll
        for (int mt = 0; mt < 2; mt++) {
            int rg = rowBase + warpM * 32 + mt * 16 + (lane >> 2);
#pragma unroll
            for (int nt = 0; nt < 4; nt++) {
                int cg = colBase + warpN * 32 + nt * 8 + 2 * (lane & 3);
                float b0 = bias[cg], b1 = bias[cg + 1];
                if (rg < M) {
                    *(float2*)(C + (size_t)rg * N + cg) =
                        make_float2(acc[mt][nt][0] + b0, acc[mt][nt][1] + b1);
                }
                if (rg + 8 < M) {
                    *(float2*)(C + (size_t)(rg + 8) * N + cg) =
                        make_float2(acc[mt][nt][2] + b0, acc[mt][nt][3] + b1);
                }
            }
        }
    } else {
        const float* b1p = ab1 + head * AA;
        const float* w2p = aw2 + head * AA;
#pragma unroll
        for (int mt = 0; mt < 2; mt++) {
            float s0 = 0.f, s1 = 0.f;
#pragma unroll
            for (int nt = 0; nt < 4; nt++) {
                int cl = colBase + warpN * 32 + nt * 8 + 2 * (lane & 3);
                float bb0 = b1p[cl], bb1 = b1p[cl + 1];
                float ww0 = w2p[cl], ww1 = w2p[cl + 1];
                s0 += tanhf(acc[mt][nt][0] + bb0) * ww0 + tanhf(acc[mt][nt][1] + bb1) * ww1;
                s1 += tanhf(acc[mt][nt][2] + bb0) * ww0 + tanhf(acc[mt][nt][3] + bb1) * ww1;
            }
            s0 += __shfl_xor_sync(0xffffffffu, s0, 1);
            s0 += __shfl_xor_sync(0xffffffffu, s0, 2);
            s1 += __shfl_xor_sync(0xffffffffu, s1, 1);
            s1 += __shfl_xor_sync(0xffffffffu, s1, 2);
            if ((lane & 3) == 0) {
                int rg = rowBase + warpM * 32 + mt * 16 + (lane >> 2);
                if (rg < M)     atomicAdd(&logits[head * NN + rg], s0);
                if (rg + 8 < M) atomicAdd(&logits[head * NN + rg + 8], s1);
            }
        }
    }
}

// ---------------- LayerNorm (+relu, + optional residual), warp per row ----------------
__global__ __launch_bounds__(256) void ln_relu_kernel(
    const float* __restrict__ in, const float* __restrict__ gamma,
    const float* __restrict__ beta, const float* __restrict__ resid,
    float* __restrict__ outp)
{
    int gtid = blockIdx.x * blockDim.x + threadIdx.x;
    int row = gtid >> 5;
    int lane = gtid & 31;
    if (row >= NN) return;
    const float* r = in + (size_t)row * HH;
    float v[8];
    float s = 0.f, sq = 0.f;
#pragma unroll
    for (int j = 0; j < 8; j++) {
        float x = r[lane + 32 * j];
        v[j] = x;
        s += x;
        sq += x * x;
    }
#pragma unroll
    for (int off = 16; off; off >>= 1) {
        s  += __shfl_xor_sync(0xffffffffu, s, off);
        sq += __shfl_xor_sync(0xffffffffu, sq, off);
    }
    float mean = s * (1.f / HH);
    float var  = sq * (1.f / HH) - mean * mean;
    float rstd = rsqrtf(var + 1e-5f);
    float* o = outp + (size_t)row * HH;
    const float* rr = resid ? resid + (size_t)row * HH : nullptr;
#pragma unroll
    for (int j = 0; j < 8; j++) {
        int c = lane + 32 * j;
        float y = (v[j] - mean) * rstd * gamma[c] + beta[c];
        y = fmaxf(y, 0.f);
        if (rr) y += rr[c];
        o[c] = y;
    }
}

// ---------------- softmax stats: one block per head ----------------
__global__ __launch_bounds__(1024) void softmax_stats_kernel() {
    int k = blockIdx.x;
    const float* l = g_logits + k * NN;
    __shared__ float red[1024];
    int tid = threadIdx.x;
    float mx = -1e30f;
    for (int i = tid; i < NN; i += 1024) mx = fmaxf(mx, l[i]);
    red[tid] = mx;
    __syncthreads();
    for (int off = 512; off; off >>= 1) {
        if (tid < off) red[tid] = fmaxf(red[tid], red[tid + off]);
        __syncthreads();
    }
    mx = red[0];
    __syncthreads();
    float s = 0.f;
    for (int i = tid; i < NN; i += 1024) s += expf(l[i] - mx);
    red[tid] = s;
    __syncthreads();
    for (int off = 512; off; off >>= 1) {
        if (tid < off) red[tid] += red[tid + off];
        __syncthreads();
    }
    if (tid == 0) {
        g_smax[k]  = mx;
        g_srsum[k] = 1.f / red[0];
    }
}

// ---------------- pooling: write attn output + accumulate z ----------------
__global__ __launch_bounds__(256) void pool_kernel(const float* __restrict__ h, float* __restrict__ out) {
    __shared__ float a_s[256 * 4];
    int tid = threadIdx.x;
    int n0 = blockIdx.x * 256;
    int n = n0 + tid;
#pragma unroll
    for (int k = 0; k < AHD; k++) {
        float a = 0.f;
        if (n < NN) {
            a = expf(g_logits[k * NN + n] - g_smax[k]) * g_srsum[k];
            out[7 + (size_t)n * AHD + k] = a;
        }
        a_s[tid * 4 + k] = a;
    }
    __syncthreads();
    float zr[4] = {0.f, 0.f, 0.f, 0.f};
    int nmax = min(256, NN - n0);
    for (int i = 0; i < nmax; i++) {
        float hv = h[(size_t)(n0 + i) * HH + tid];
        float4 av = *(float4*)&a_s[i * 4];
        zr[0] += av.x * hv;
        zr[1] += av.y * hv;
        zr[2] += av.z * hv;
        zr[3] += av.w * hv;
    }
#pragma unroll
    for (int k = 0; k < AHD; k++) atomicAdd(&g_z[k * HH + tid], zr[k]);
}

// ---------------- classifier: single block ----------------
__global__ __launch_bounds__(256) void classifier_kernel(
    const float* __restrict__ Wc1, const float* __restrict__ bc1,
    const float* __restrict__ g1,  const float* __restrict__ b1,
    const float* __restrict__ Wc2, const float* __restrict__ bc2,
    const float* __restrict__ g2,  const float* __restrict__ b2,
    const float* __restrict__ Wc3, const float* __restrict__ bc3,
    float* __restrict__ out)
{
    __shared__ float sh[256];
    __shared__ float redA[256];
    __shared__ float redB[256];
    int tid = threadIdx.x;
    float za = 0.25f * (g_z[tid] + g_z[256 + tid] + g_z[512 + tid] + g_z[768 + tid]);
    sh[tid] = za;
    __syncthreads();

    float c = 0.f;
    if (tid < 128) {
        for (int d = 0; d < 256; d++) c += sh[d] * Wc1[d * 128 + tid];
        c += bc1[tid];
    }
    redA[tid] = (tid < 128) ? c : 0.f;
    redB[tid] = (tid < 128) ? c * c : 0.f;
    __syncthreads();
    for (int off = 128; off; off >>= 1) {
        if (tid < off) { redA[tid] += redA[tid + off]; redB[tid] += redB[tid + off]; }
        __syncthreads();
    }
    float mean = redA[0] / 128.f;
    float var  = redB[0] / 128.f - mean * mean;
    float rstd = rsqrtf(var + 1e-5f);
    __syncthreads();
    if (tid < 128) sh[tid] = fmaxf((c - mean) * rstd * g1[tid] + b1[tid], 0.f);
    __syncthreads();

    float c2 = 0.f;
    if (tid < 64) {
        for (int d = 0; d < 128; d++) c2 += sh[d] * Wc2[d * 64 + tid];
        c2 += bc2[tid];
    }
    redA[tid] = (tid < 64) ? c2 : 0.f;
    redB[tid] = (tid < 64) ? c2 * c2 : 0.f;
    __syncthreads();
    for (int off = 128; off; off >>= 1) {
        if (tid < off) { redA[tid] += redA[tid + off]; redB[tid] += redB[tid + off]; }
        __syncthreads();
    }
    mean = redA[0] / 64.f;
    var  = redB[0] / 64.f - mean * mean;
    rstd = rsqrtf(var + 1e-5f);
    __syncthreads();
    if (tid < 64) sh[tid] = fmaxf((c2 - mean) * rstd * g2[tid] + b2[tid], 0.f);
    __syncthreads();

    if (tid < NCLS) {
        float lg = 0.f;
        for (int d = 0; d < 64; d++) lg += sh[d] * Wc3[d * NCLS + tid];
        redA[tid] = lg + bc3[tid];
    }
    __syncthreads();
    if (tid == 0) {
        float mx = -1e30f;
        for (int i = 0; i < NCLS; i++) mx = fmaxf(mx, redA[i]);
        float s = 0.f;
        for (int i = 0; i < NCLS; i++) s += expf(redA[i] - mx);
        float rs = 1.f / s;
        for (int i = 0; i < NCLS; i++) out[i] = expf(redA[i] - mx) * rs;
    }
}

// ---------------- launcher ----------------
extern "C" void kernel_launch(void* const* d_in, const int* in_sizes, int n_in,
                              void* d_out, int out_size)
{
    const float* x     = (const float*)d_in[0];
    const int*   ei    = (const int*)  d_in[1];
    const float* W_in  = (const float*)d_in[2];
    const float* b_in  = (const float*)d_in[3];
    const float* gW1   = (const float*)d_in[4];
    const float* gb1   = (const float*)d_in[5];
    const float* glng  = (const float*)d_in[6];
    const float* glnb  = (const float*)d_in[7];
    const float* gW2   = (const float*)d_in[8];
    const float* gb2   = (const float*)d_in[9];
    const float* eps   = (const float*)d_in[10];
    const float* lng   = (const float*)d_in[11];
    const float* lnb   = (const float*)d_in[12];
    const float* aW1   = (const float*)d_in[13];
    const float* ab1   = (const float*)d_in[14];
    const float* aW2   = (const float*)d_in[15];
    const float* ab2   = (const float*)d_in[16];
    const float* Wc1   = (const float*)d_in[17];
    const float* bc1   = (const float*)d_in[18];
    const float* lc1g  = (const float*)d_in[19];
    const float* lc1b  = (const float*)d_in[20];
    const float* Wc2   = (const float*)d_in[21];
    const float* bc2   = (const float*)d_in[22];
    const float* lc2g  = (const float*)d_in[23];
    const float* lc2b  = (const float*)d_in[24];
    const float* Wc3   = (const float*)d_in[25];
    const float* bc3   = (const float*)d_in[26];
    float* out = (float*)d_out;
    (void)ab2;

    float *p_h, *p_agg, *p_t, *p_logits;
    cudaGetSymbolAddress((void**)&p_h, g_h);
    cudaGetSymbolAddress((void**)&p_agg, g_agg);
    cudaGetSymbolAddress((void**)&p_t, g_t);
    cudaGetSymbolAddress((void**)&p_logits, g_logits);

    const int SMEM_BYTES = TFS_SMEM_WORDS * 4;   // 55296
    cudaFuncSetAttribute(gemm_tf32_kernel<0>, cudaFuncAttributeMaxDynamicSharedMemorySize, SMEM_BYTES);
    cudaFuncSetAttribute(gemm_tf32_kernel<1>, cudaFuncAttributeMaxDynamicSharedMemorySize, SMEM_BYTES);

    const int MB = (NN + 127) / 128;               // 391 row tiles
    const int WARP_BLKS = (NN * 32 + 255) / 256;   // 6250
    const int ROW_BLKS  = (NN + 7) / 8;            // 6250
    const int EDGE_BLKS = (EE + 255) / 256;        // 3125
    const int POOL_BLKS = (NN + 255) / 256;        // 196
    const int ZERO_BLKS = (AHD * NN + 255) / 256;  // 782

    // CSR build + scratch zero
    zero_kernel<<<ZERO_BLKS, 256>>>();
    hist_kernel<<<EDGE_BLKS, 256>>>(ei);
    scan_kernel<<<1, 1024>>>();
    fill_kernel<<<EDGE_BLKS, 256>>>(ei);

    // input projection: h = x @ W_in + b_in   (tf32 split GEMM)
    gemm_tf32_kernel<0><<<dim3(HH / 64, MB), 256, SMEM_BYTES>>>(
        x, W_in, b_in, p_h, NN, HH, FF, nullptr, nullptr, nullptr);

    // GIN layers
    for (int l = 0; l < 2; l++) {
        gin_agg_kernel<<<WARP_BLKS, 256>>>(eps, l);
        gemm_tf32_kernel<0><<<dim3(HH / 64, MB), 256, SMEM_BYTES>>>(
            p_agg, gW1 + (size_t)l * HH * HH, gb1 + l * HH, p_t,
            NN, HH, HH, nullptr, nullptr, nullptr);
        ln_relu_kernel<<<ROW_BLKS, 256>>>(p_t, glng + l * HH, glnb + l * HH, nullptr, p_t);
        gemm_tf32_kernel<0><<<dim3(HH / 64, MB), 256, SMEM_BYTES>>>(
            p_t, gW2 + (size_t)l * HH * HH, gb2 + l * HH, p_agg,
            NN, HH, HH, nullptr, nullptr, nullptr);
        ln_relu_kernel<<<ROW_BLKS, 256>>>(p_agg, lng + l * HH, lnb + l * HH, p_h, p_h);
    }

    // attention logits: fused tanh(h@W1 + b1)·W2 partial reduce into g_logits
    // (b2 omitted: constant shift per head, softmax-invariant)
    gemm_tf32_kernel<1><<<dim3(AA / 64, MB, AHD), 256, SMEM_BYTES>>>(
        p_h, aW1, nullptr, nullptr, NN, AA, HH, ab1, aW2, p_logits);

    softmax_stats_kernel<<<AHD, 1024>>>();
    pool_kernel<<<POOL_BLKS, 256>>>(p_h, out);

    // classifier head
    classifier_kernel<<<1, 256>>>(Wc1, bc1, lc1g, lc1b, Wc2, bc2, lc2g, lc2b, Wc3, bc3, out);
}

// round 14
// speedup vs baseline: 1.5885x; 1.3764x over previous
#include <cuda_runtime.h>
#include <cuda_bf16.h>
#include <math.h>
#include <stdint.h>

#define NN   50000
#define EE   800000
#define FF   768
#define HH   256
#define AA   128
#define AHD  4
#define NCLS 7

// ---------------- scratch (no allocations allowed) ----------------
__device__ __align__(16) float g_h[(size_t)NN * HH];
__device__ __align__(16) float g_agg[(size_t)NN * HH];
__device__ __align__(16) float g_t[(size_t)NN * HH];
__device__ int   g_deg[NN];
__device__ int   g_rowstart[NN + 1];
__device__ int   g_cursor[NN];
__device__ int   g_srclist[EE];
__device__ float g_logits[AHD * NN];
__device__ float g_smax[AHD];
__device__ float g_srsum[AHD];
__device__ float g_z[AHD * HH];

// ---------------- small utility kernels ----------------
__global__ void zero_kernel() {
    int i = blockIdx.x * blockDim.x + threadIdx.x;
    if (i < NN) g_deg[i] = 0;
    if (i < AHD * HH) g_z[i] = 0.f;
    if (i < AHD * NN) g_logits[i] = 0.f;
}

__global__ void hist_kernel(const int* __restrict__ ei) {
    int e = blockIdx.x * blockDim.x + threadIdx.x;
    if (e < EE) atomicAdd(&g_deg[ei[EE + e]], 1);
}

__global__ __launch_bounds__(1024) void scan_kernel() {
    __shared__ int ssum[1024];
    int tid = threadIdx.x;
    const int CH = (NN + 1023) / 1024;
    int base = tid * CH;
    int s = 0;
    for (int i = 0; i < CH; i++) {
        int idx = base + i;
        if (idx < NN) s += g_deg[idx];
    }
    ssum[tid] = s;
    __syncthreads();
    for (int off = 1; off < 1024; off <<= 1) {
        int v = 0;
        if (tid >= off) v = ssum[tid - off];
        __syncthreads();
        ssum[tid] += v;
        __syncthreads();
    }
    int run = (tid == 0) ? 0 : ssum[tid - 1];
    for (int i = 0; i < CH; i++) {
        int idx = base + i;
        if (idx < NN) {
            g_rowstart[idx] = run;
            g_cursor[idx]   = run;
            run += g_deg[idx];
        }
    }
    if (tid == 1023) g_rowstart[NN] = run;
}

__global__ void fill_kernel(const int* __restrict__ ei) {
    int e = blockIdx.x * blockDim.x + threadIdx.x;
    if (e < EE) {
        int d = ei[EE + e];
        int pos = atomicAdd(&g_cursor[d], 1);
        g_srclist[pos] = ei[e];
    }
}

// ---------------- GIN aggregation: one warp per destination node ----------------
__device__ __forceinline__ float4 f4add(float4 a, float4 b) {
    return make_float4(a.x + b.x, a.y + b.y, a.z + b.z, a.w + b.w);
}

__global__ __launch_bounds__(256) void gin_agg_kernel(const float* __restrict__ epsv, int layer) {
    int gtid = blockIdx.x * blockDim.x + threadIdx.x;
    int node = gtid >> 5;
    int lane = gtid & 31;
    if (node >= NN) return;
    int s = g_rowstart[node];
    int e = g_rowstart[node + 1];
    float4 acc0 = make_float4(0, 0, 0, 0);
    float4 acc1 = make_float4(0, 0, 0, 0);
    for (int i = s; i < e; i++) {
        int src = g_srclist[i];
        const float4* r = (const float4*)(g_h + (size_t)src * HH);
        acc0 = f4add(acc0, r[lane]);
        acc1 = f4add(acc1, r[lane + 32]);
    }
    float ep = 1.f + epsv[layer];
    const float4* hr = (const float4*)(g_h + (size_t)node * HH);
    float4 h0 = hr[lane], h1 = hr[lane + 32];
    float4* ar = (float4*)(g_agg + (size_t)node * HH);
    ar[lane]      = make_float4(ep * h0.x + acc0.x, ep * h0.y + acc0.y, ep * h0.z + acc0.z, ep * h0.w + acc0.w);
    ar[lane + 32] = make_float4(ep * h1.x + acc1.x, ep * h1.y + acc1.y, ep * h1.z + acc1.z, ep * h1.w + acc1.w);
}

// ---------------- split-bf16 tensor-core GEMM ----------------
// C[M,N] = A[M,K] @ B[K,N] via mma.sync.m16n8k16.bf16 with 3-term hi/lo split.
// Block tile 128x64, K-chunk 32, 8 warps (warpM 0-3 x warpN 0-1), warp tile 32x32.
// MODE 0: C = A@B + bias
// MODE 1: attention epilogue -> logits[head][row] += sum_col tanh(acc + b1)*w2

__device__ __forceinline__ void split2(float x, float y, uint32_t& hi, uint32_t& lo) {
    __nv_bfloat16 hx = __float2bfloat16(x), hy = __float2bfloat16(y);
    float rx = x - __bfloat162float(hx), ry = y - __bfloat162float(hy);
    __nv_bfloat16 lx = __float2bfloat16(rx), ly = __float2bfloat16(ry);
    hi = (uint32_t)(*(unsigned short*)&hx) | ((uint32_t)(*(unsigned short*)&hy) << 16);
    lo = (uint32_t)(*(unsigned short*)&lx) | ((uint32_t)(*(unsigned short*)&ly) << 16);
}

__device__ __forceinline__ void mma16(float* d, const uint32_t* a, const uint32_t* b) {
    asm volatile(
        "mma.sync.aligned.m16n8k16.row.col.f32.bf16.bf16.f32 "
        "{%0,%1,%2,%3}, {%4,%5,%6,%7}, {%8,%9}, {%0,%1,%2,%3};"
        : "+f"(d[0]), "+f"(d[1]), "+f"(d[2]), "+f"(d[3])
        : "r"(a[0]), "r"(a[1]), "r"(a[2]), "r"(a[3]), "r"(b[0]), "r"(b[1]));
}

// smem word layout: 16 k-pair words per row, stride 17 (conflict-free)
#define AST 17

template <int MODE>
__global__ __launch_bounds__(256, 2) void gemm_bf16_kernel(
    const float* __restrict__ A, const float* __restrict__ Bm,
    const float* __restrict__ bias, float* __restrict__ C,
    int M, int N, int K,
    const float* __restrict__ ab1, const float* __restrict__ aw2,
    float* __restrict__ logits)
{
    __shared__ uint32_t Ah[128 * AST];
    __shared__ uint32_t Al[128 * AST];
    __shared__ uint32_t Bh[64 * AST];
    __shared__ uint32_t Bl[64 * AST];

    int tid = threadIdx.x;
    int wid = tid >> 5;
    int lane = tid & 31;
    int warpM = wid >> 1;          // 0..3 (32 rows each)
    int warpN = wid & 1;           // 0..1 (32 cols each)
    int rowBase = blockIdx.y * 128;
    int colBase = blockIdx.x * 64;
    int head = (MODE == 1) ? blockIdx.z : 0;
    const float* B = (MODE == 1) ? Bm + (size_t)head * HH * AA : Bm;

    float acc[2][4][4];
#pragma unroll
    for (int mt = 0; mt < 2; mt++)
#pragma unroll
        for (int nt = 0; nt < 4; nt++)
#pragma unroll
            for (int r = 0; r < 4; r++) acc[mt][nt][r] = 0.f;

    for (int k0 = 0; k0 < K; k0 += 32) {
        // ---- stage A (128x32) -> packed bf16 hi/lo k-pairs ----
#pragma unroll
        for (int i = 0; i < 4; i++) {
            int f4id = tid + 256 * i;          // 0..1023
            int row = f4id >> 3;               // 8 float4 per row
            int kc = (f4id & 7) << 2;          // k offset 0,4,..,28
            int grow = rowBase + row;
            float4 v = make_float4(0, 0, 0, 0);
            if (grow < M) v = *(const float4*)(A + (size_t)grow * K + k0 + kc);
            uint32_t h01, l01, h23, l23;
            split2(v.x, v.y, h01, l01);
            split2(v.z, v.w, h23, l23);
            int w = row * AST + (kc >> 1);
            Ah[w] = h01; Ah[w + 1] = h23;
            Al[w] = l01; Al[w + 1] = l23;
        }
        // ---- stage B (32x64) transposed: Bs[n][kpair] ----
#pragma unroll
        for (int i = 0; i < 2; i++) {
            int g = tid + 256 * i;             // 0..511
            int n = g & 63;
            int kq = g >> 6;                   // 0..7 (k = 4*kq)
            int k = kq << 2;
            const float* bp = B + (size_t)(k0 + k) * N + colBase + n;
            float v0 = bp[0], v1 = bp[N], v2 = bp[2 * N], v3 = bp[3 * N];
            uint32_t h01, l01, h23, l23;
            split2(v0, v1, h01, l01);
            split2(v2, v3, h23, l23);
            int w = n * AST + (kq << 1);
            Bh[w] = h01; Bh[w + 1] = h23;
            Bl[w] = l01; Bl[w + 1] = l23;
        }
        __syncthreads();

#pragma unroll
        for (int ks = 0; ks < 2; ks++) {
            int kw = ks * 8;
            uint32_t Af_h[2][4], Af_l[2][4];
#pragma unroll
            for (int mt = 0; mt < 2; mt++) {
                int mrow = warpM * 32 + mt * 16 + (lane >> 2);
                int base = mrow * AST + kw + (lane & 3);
                Af_h[mt][0] = Ah[base];
                Af_h[mt][1] = Ah[base + 8 * AST];
                Af_h[mt][2] = Ah[base + 4];
                Af_h[mt][3] = Ah[base + 8 * AST + 4];
                Af_l[mt][0] = Al[base];
                Af_l[mt][1] = Al[base + 8 * AST];
                Af_l[mt][2] = Al[base + 4];
                Af_l[mt][3] = Al[base + 8 * AST + 4];
            }
            uint32_t Bf_h[4][2], Bf_l[4][2];
#pragma unroll
            for (int nt = 0; nt < 4; nt++) {
                int n = warpN * 32 + nt * 8 + (lane >> 2);
                int bb = n * AST + kw + (lane & 3);
                Bf_h[nt][0] = Bh[bb];
                Bf_h[nt][1] = Bh[bb + 4];
                Bf_l[nt][0] = Bl[bb];
                Bf_l[nt][1] = Bl[bb + 4];
            }
#pragma unroll
            for (int mt = 0; mt < 2; mt++)
#pragma unroll
                for (int nt = 0; nt < 4; nt++) {
                    mma16(acc[mt][nt], Af_h[mt], Bf_h[nt]);
                    mma16(acc[mt][nt], Af_h[mt], Bf_l[nt]);
                    mma16(acc[mt][nt], Af_l[mt], Bf_h[nt]);
                }
        }
        __syncthreads();
    }

    if (MODE == 0) {
#pragma unroll
        for (int mt = 0; mt < 2; mt++) {
            int rg = rowBase + warpM * 32 + mt * 16 + (lane >> 2);
#pragma unroll
            for (int nt = 0; nt < 4; nt++) {
                int cg = colBase + warpN * 32 + nt * 8 + 2 * (lane & 3);
                float b0 = bias[cg], b1 = bias[cg + 1];
                if (rg < M) {
                    *(float2*)(C + (size_t)rg * N + cg) =
                        make_float2(acc[mt][nt][0] + b0, acc[mt][nt][1] + b1);
                }
                if (rg + 8 < M) {
                    *(float2*)(C + (size_t)(rg + 8) * N + cg) =
                        make_float2(acc[mt][nt][2] + b0, acc[mt][nt][3] + b1);
                }
            }
        }
    } else {
        const float* b1p = ab1 + head * AA;
        const float* w2p = aw2 + head * AA;
#pragma unroll
        for (int mt = 0; mt < 2; mt++) {
            float s0 = 0.f, s1 = 0.f;
#pragma unroll
            for (int nt = 0; nt < 4; nt++) {
                int cl = colBase + warpN * 32 + nt * 8 + 2 * (lane & 3);
                float bb0 = b1p[cl], bb1 = b1p[cl + 1];
                float ww0 = w2p[cl], ww1 = w2p[cl + 1];
                s0 += tanhf(acc[mt][nt][0] + bb0) * ww0 + tanhf(acc[mt][nt][1] + bb1) * ww1;
                s1 += tanhf(acc[mt][nt][2] + bb0) * ww0 + tanhf(acc[mt][nt][3] + bb1) * ww1;
            }
            s0 += __shfl_xor_sync(0xffffffffu, s0, 1);
            s0 += __shfl_xor_sync(0xffffffffu, s0, 2);
            s1 += __shfl_xor_sync(0xffffffffu, s1, 1);
            s1 += __shfl_xor_sync(0xffffffffu, s1, 2);
            if ((lane & 3) == 0) {
                int rg = rowBase + warpM * 32 + mt * 16 + (lane >> 2);
                if (rg < M)     atomicAdd(&logits[head * NN + rg], s0);
                if (rg + 8 < M) atomicAdd(&logits[head * NN + rg + 8], s1);
            }
        }
    }
}

// ---------------- LayerNorm (+relu, + optional residual), warp per row ----------------
__global__ __launch_bounds__(256) void ln_relu_kernel(
    const float* __restrict__ in, const float* __restrict__ gamma,
    const float* __restrict__ beta, const float* __restrict__ resid,
    float* __restrict__ outp)
{
    int gtid = blockIdx.x * blockDim.x + threadIdx.x;
    int row = gtid >> 5;
    int lane = gtid & 31;
    if (row >= NN) return;
    const float* r = in + (size_t)row * HH;
    float v[8];
    float s = 0.f, sq = 0.f;
#pragma unroll
    for (int j = 0; j < 8; j++) {
        float x = r[lane + 32 * j];
        v[j] = x;
        s += x;
        sq += x * x;
    }
#pragma unroll
    for (int off = 16; off; off >>= 1) {
        s  += __shfl_xor_sync(0xffffffffu, s, off);
        sq += __shfl_xor_sync(0xffffffffu, sq, off);
    }
    float mean = s * (1.f / HH);
    float var  = sq * (1.f / HH) - mean * mean;
    float rstd = rsqrtf(var + 1e-5f);
    float* o = outp + (size_t)row * HH;
    const float* rr = resid ? resid + (size_t)row * HH : nullptr;
#pragma unroll
    for (int j = 0; j < 8; j++) {
        int c = lane + 32 * j;
        float y = (v[j] - mean) * rstd * gamma[c] + beta[c];
        y = fmaxf(y, 0.f);
        if (rr) y += rr[c];
        o[c] = y;
    }
}

// ---------------- softmax stats: one block per head ----------------
__global__ __launch_bounds__(1024) void softmax_stats_kernel() {
    int k = blockIdx.x;
    const float* l = g_logits + k * NN;
    __shared__ float red[1024];
    int tid = threadIdx.x;
    float mx = -1e30f;
    for (int i = tid; i < NN; i += 1024) mx = fmaxf(mx, l[i]);
    red[tid] = mx;
    __syncthreads();
    for (int off = 512; off; off >>= 1) {
        if (tid < off) red[tid] = fmaxf(red[tid], red[tid + off]);
        __syncthreads();
    }
    mx = red[0];
    __syncthreads();
    float s = 0.f;
    for (int i = tid; i < NN; i += 1024) s += expf(l[i] - mx);
    red[tid] = s;
    __syncthreads();
    for (int off = 512; off; off >>= 1) {
        if (tid < off) red[tid] += red[tid + off];
        __syncthreads();
    }
    if (tid == 0) {
        g_smax[k]  = mx;
        g_srsum[k] = 1.f / red[0];
    }
}

// ---------------- pooling: write attn output + accumulate z ----------------
__global__ __launch_bounds__(256) void pool_kernel(const float* __restrict__ h, float* __restrict__ out) {
    __shared__ float a_s[256 * 4];
    int tid = threadIdx.x;
    int n0 = blockIdx.x * 256;
    int n = n0 + tid;
#pragma unroll
    for (int k = 0; k < AHD; k++) {
        float a = 0.f;
        if (n < NN) {
            a = expf(g_logits[k * NN + n] - g_smax[k]) * g_srsum[k];
            out[7 + (size_t)n * AHD + k] = a;
        }
        a_s[tid * 4 + k] = a;
    }
    __syncthreads();
    float zr[4] = {0.f, 0.f, 0.f, 0.f};
    int nmax = min(256, NN - n0);
    for (int i = 0; i < nmax; i++) {
        float hv = h[(size_t)(n0 + i) * HH + tid];
        float4 av = *(float4*)&a_s[i * 4];
        zr[0] += av.x * hv;
        zr[1] += av.y * hv;
        zr[2] += av.z * hv;
        zr[3] += av.w * hv;
    }
#pragma unroll
    for (int k = 0; k < AHD; k++) atomicAdd(&g_z[k * HH + tid], zr[k]);
}

// ---------------- classifier: single block ----------------
__global__ __launch_bounds__(256) void classifier_kernel(
    const float* __restrict__ Wc1, const float* __restrict__ bc1,
    const float* __restrict__ g1,  const float* __restrict__ b1,
    const float* __restrict__ Wc2, const float* __restrict__ bc2,
    const float* __restrict__ g2,  const float* __restrict__ b2,
    const float* __restrict__ Wc3, const float* __restrict__ bc3,
    float* __restrict__ out)
{
    __shared__ float sh[256];
    __shared__ float redA[256];
    __shared__ float redB[256];
    int tid = threadIdx.x;
    float za = 0.25f * (g_z[tid] + g_z[256 + tid] + g_z[512 + tid] + g_z[768 + tid]);
    sh[tid] = za;
    __syncthreads();

    float c = 0.f;
    if (tid < 128) {
        for (int d = 0; d < 256; d++) c += sh[d] * Wc1[d * 128 + tid];
        c += bc1[tid];
    }
    redA[tid] = (tid < 128) ? c : 0.f;
    redB[tid] = (tid < 128) ? c * c : 0.f;
    __syncthreads();
    for (int off = 128; off; off >>= 1) {
        if (tid < off) { redA[tid] += redA[tid + off]; redB[tid] += redB[tid + off]; }
        __syncthreads();
    }
    float mean = redA[0] / 128.f;
    float var  = redB[0] / 128.f - mean * mean;
    float rstd = rsqrtf(var + 1e-5f);
    __syncthreads();
    if (tid < 128) sh[tid] = fmaxf((c - mean) * rstd * g1[tid] + b1[tid], 0.f);
    __syncthreads();

    float c2 = 0.f;
    if (tid < 64) {
        for (int d = 0; d < 128; d++) c2 += sh[d] * Wc2[d * 64 + tid];
        c2 += bc2[tid];
    }
    redA[tid] = (tid < 64) ? c2 : 0.f;
    redB[tid] = (tid < 64) ? c2 * c2 : 0.f;
    __syncthreads();
    for (int off = 128; off; off >>= 1) {
        if (tid < off) { redA[tid] += redA[tid + off]; redB[tid] += redB[tid + off]; }
        __syncthreads();
    }
    mean = redA[0] / 64.f;
    var  = redB[0] / 64.f - mean * mean;
    rstd = rsqrtf(var + 1e-5f);
    __syncthreads();
    if (tid < 64) sh[tid] = fmaxf((c2 - mean) * rstd * g2[tid] + b2[tid], 0.f);
    __syncthreads();

    if (tid < NCLS) {
        float lg = 0.f;
        for (int d = 0; d < 64; d++) lg += sh[d] * Wc3[d * NCLS + tid];
        redA[tid] = lg + bc3[tid];
    }
    __syncthreads();
    if (tid == 0) {
        float mx = -1e30f;
        for (int i = 0; i < NCLS; i++) mx = fmaxf(mx, redA[i]);
        float s = 0.f;
        for (int i = 0; i < NCLS; i++) s += expf(redA[i] - mx);
        float rs = 1.f / s;
        for (int i = 0; i < NCLS; i++) out[i] = expf(redA[i] - mx) * rs;
    }
}

// ---------------- launcher ----------------
extern "C" void kernel_launch(void* const* d_in, const int* in_sizes, int n_in,
                              void* d_out, int out_size)
{
    const float* x     = (const float*)d_in[0];
    const int*   ei    = (const int*)  d_in[1];
    const float* W_in  = (const float*)d_in[2];
    const float* b_in  = (const float*)d_in[3];
    const float* gW1   = (const float*)d_in[4];
    const float* gb1   = (const float*)d_in[5];
    const float* glng  = (const float*)d_in[6];
    const float* glnb  = (const float*)d_in[7];
    const float* gW2   = (const float*)d_in[8];
    const float* gb2   = (const float*)d_in[9];
    const float* eps   = (const float*)d_in[10];
    const float* lng   = (const float*)d_in[11];
    const float* lnb   = (const float*)d_in[12];
    const float* aW1   = (const float*)d_in[13];
    const float* ab1   = (const float*)d_in[14];
    const float* aW2   = (const float*)d_in[15];
    const float* Wc1   = (const float*)d_in[17];
    const float* bc1   = (const float*)d_in[18];
    const float* lc1g  = (const float*)d_in[19];
    const float* lc1b  = (const float*)d_in[20];
    const float* Wc2   = (const float*)d_in[21];
    const float* bc2   = (const float*)d_in[22];
    const float* lc2g  = (const float*)d_in[23];
    const float* lc2b  = (const float*)d_in[24];
    const float* Wc3   = (const float*)d_in[25];
    const float* bc3   = (const float*)d_in[26];
    float* out = (float*)d_out;

    float *p_h, *p_agg, *p_t, *p_logits;
    cudaGetSymbolAddress((void**)&p_h, g_h);
    cudaGetSymbolAddress((void**)&p_agg, g_agg);
    cudaGetSymbolAddress((void**)&p_t, g_t);
    cudaGetSymbolAddress((void**)&p_logits, g_logits);

    const int MB = (NN + 127) / 128;               // 391 row tiles
    const int WARP_BLKS = (NN * 32 + 255) / 256;   // 6250
    const int ROW_BLKS  = (NN + 7) / 8;            // 6250
    const int EDGE_BLKS = (EE + 255) / 256;        // 3125
    const int POOL_BLKS = (NN + 255) / 256;        // 196
    const int ZERO_BLKS = (AHD * NN + 255) / 256;  // 782

    // CSR build + scratch zero (logits zeroed for attention atomics)
    zero_kernel<<<ZERO_BLKS, 256>>>();
    hist_kernel<<<EDGE_BLKS, 256>>>(ei);
    scan_kernel<<<1, 1024>>>();
    fill_kernel<<<EDGE_BLKS, 256>>>(ei);

    // input projection: h = x @ W_in + b_in   (split-bf16 GEMM)
    gemm_bf16_kernel<0><<<dim3(HH / 64, MB), 256>>>(
        x, W_in, b_in, p_h, NN, HH, FF, nullptr, nullptr, nullptr);

    // GIN layers
    for (int l = 0; l < 2; l++) {
        gin_agg_kernel<<<WARP_BLKS, 256>>>(eps, l);
        gemm_bf16_kernel<0><<<dim3(HH / 64, MB), 256>>>(
            p_agg, gW1 + (size_t)l * HH * HH, gb1 + l * HH, p_t,
            NN, HH, HH, nullptr, nullptr, nullptr);
        ln_relu_kernel<<<ROW_BLKS, 256>>>(p_t, glng + l * HH, glnb + l * HH, nullptr, p_t);
        gemm_bf16_kernel<0><<<dim3(HH / 64, MB), 256>>>(
            p_t, gW2 + (size_t)l * HH * HH, gb2 + l * HH, p_agg,
            NN, HH, HH, nullptr, nullptr, nullptr);
        ln_relu_kernel<<<ROW_BLKS, 256>>>(p_agg, lng + l * HH, lnb + l * HH, p_h, p_h);
    }

    // attention logits: fused tanh(h@W1 + b1)·W2 partial reduce into g_logits
    // (b2 omitted: constant shift per head, softmax-invariant)
    gemm_bf16_kernel<1><<<dim3(AA / 64, MB, AHD), 256>>>(
        p_h, aW1, nullptr, nullptr, NN, AA, HH, ab1, aW2, p_logits);

    softmax_stats_kernel<<<AHD, 1024>>>();
    pool_kernel<<<POOL_BLKS, 256>>>(p_h, out);

    // classifier head
    classifier_kernel<<<1, 256>>>(Wc1, bc1, lc1g, lc1b, Wc2, bc2, lc2g, lc2b, Wc3, bc3, out);
}